// round 12
// baseline (speedup 1.0000x reference)
#include <cuda_runtime.h>
#include <math.h>

#define NMAX 50000
#define EMAX 800000
#define HID 96
#define HEADS 4
#define DHEAD 24
#define RMAX 64
#define NEG_SLOPE 0.2f

// ---- device scratch (no allocations allowed) ----
__device__ float    g_h[NMAX * HID];          // x @ W
__device__ float    g_ssrc[NMAX * HEADS];     // per-node src attention scalar
__device__ float    g_sdst[NMAX * HEADS];     // per-node dst attention scalar
__device__ float    g_rel_logit[RMAX * HEADS];
__device__ int      g_cnt[NMAX];
__device__ int      g_off[NMAX + 1];
__device__ int      g_cur[NMAX];
__device__ unsigned g_csr_packed[EMAX];       // (src<<6) | type
__device__ int      g_csr_eid[EMAX];

__device__ __forceinline__ float gelu_tanh(float v) {
    float c = v + 0.044715f * v * v * v;
    return 0.5f * v * (1.0f + tanhf(0.7978845608028654f * c));
}

// ---- 1. h = x @ W  (warp covers one node, 32 consecutive output cols) ----
__global__ void k_gemm(const float* __restrict__ x, const float* __restrict__ W, int n) {
    int t = blockIdx.x * blockDim.x + threadIdx.x;
    if (t >= n * HID) return;
    int node = t / HID;
    int j = t - node * HID;
    const float* xr = x + node * HID;
    float acc = 0.0f;
#pragma unroll 8
    for (int k = 0; k < HID; k++)
        acc = fmaf(xr[k], W[k * HID + j], acc);
    g_h[t] = acc;
}

// ---- 2. per-node attention scalars ----
__global__ void k_nodescore(const float* __restrict__ att_src,
                            const float* __restrict__ att_dst, int n) {
    int t = blockIdx.x * blockDim.x + threadIdx.x;
    if (t >= n * HEADS) return;
    int node = t / HEADS;
    int h = t - node * HEADS;
    const float* hr = g_h + node * HID + h * DHEAD;
    float s1 = 0.0f, s2 = 0.0f;
#pragma unroll
    for (int d = 0; d < DHEAD; d++) {
        float v = hr[d];
        s1 = fmaf(v, att_src[h * DHEAD + d], s1);
        s2 = fmaf(v, att_dst[h * DHEAD + d], s2);
    }
    g_ssrc[t] = s1;
    g_sdst[t] = s2;
}

// ---- 3. per-relation attention scalars ----
__global__ void k_rel(const float* __restrict__ rel_emb,
                      const float* __restrict__ att_rel, int r) {
    int t = blockIdx.x * blockDim.x + threadIdx.x;
    if (t >= r * HEADS) return;
    int rr = t / HEADS;
    int h = t - rr * HEADS;
    float s = 0.0f;
#pragma unroll
    for (int d = 0; d < DHEAD; d++)
        s = fmaf(rel_emb[rr * HID + h * DHEAD + d], att_rel[h * DHEAD + d], s);
    g_rel_logit[t] = s;
}

// ---- 4. CSR build ----
__global__ void k_zero(int n) {
    int t = blockIdx.x * blockDim.x + threadIdx.x;
    if (t < n) g_cnt[t] = 0;
}

__global__ void k_count(const int* __restrict__ ei, int e) {
    int t = blockIdx.x * blockDim.x + threadIdx.x;
    if (t < e) atomicAdd(&g_cnt[ei[e + t]], 1);
}

// single-block exclusive scan over g_cnt -> g_off, g_cur; g_off[n] = total
__global__ void k_scan(int n) {
    __shared__ int warp_sums[32];
    __shared__ int s_carry;
    int tid = threadIdx.x, lane = tid & 31, wid = tid >> 5;
    if (tid == 0) s_carry = 0;
    __syncthreads();
    int nch = (n + 1023) / 1024;
    for (int c = 0; c < nch; c++) {
        int i = c * 1024 + tid;
        int v = (i < n) ? g_cnt[i] : 0;
        int xv = v;
#pragma unroll
        for (int o = 1; o < 32; o <<= 1) {
            int y = __shfl_up_sync(0xFFFFFFFFu, xv, o);
            if (lane >= o) xv += y;
        }
        if (lane == 31) warp_sums[wid] = xv;
        __syncthreads();
        if (wid == 0) {
            int w = warp_sums[lane];
#pragma unroll
            for (int o = 1; o < 32; o <<= 1) {
                int y = __shfl_up_sync(0xFFFFFFFFu, w, o);
                if (lane >= o) w += y;
            }
            warp_sums[lane] = w;
        }
        __syncthreads();
        int wprev = (wid > 0) ? warp_sums[wid - 1] : 0;
        int incl = xv + wprev;
        int carry = s_carry;
        if (i < n) {
            int ex = carry + incl - v;
            g_off[i] = ex;
            g_cur[i] = ex;
        }
        __syncthreads();
        if (tid == 1023) s_carry = carry + incl;
        __syncthreads();
    }
    if (tid == 0) g_off[n] = s_carry;
}

__global__ void k_fill(const int* __restrict__ ei, const int* __restrict__ et, int e) {
    int t = blockIdx.x * blockDim.x + threadIdx.x;
    if (t >= e) return;
    int src = ei[t];
    int dst = ei[e + t];
    int ty = et[t];
    int pos = atomicAdd(&g_cur[dst], 1);
    g_csr_packed[pos] = ((unsigned)src << 6) | (unsigned)ty;
    g_csr_eid[pos] = t;
}

// ---- 5. warp-per-node: segment softmax + weighted message aggregation ----
__global__ void __launch_bounds__(256) k_agg(const float* __restrict__ rel_emb,
                                             const float* __restrict__ bias,
                                             float* __restrict__ out,
                                             float* __restrict__ alpha_out, int n) {
    __shared__ float    sh_alpha[8][32][HEADS];
    __shared__ unsigned sh_p[8][32];
    int wslot = threadIdx.x >> 5;
    int lane = threadIdx.x & 31;
    int node = blockIdx.x * 8 + wslot;
    if (node >= n) return;

    int start = g_off[node];
    int end = g_off[node + 1];

    float sdst0 = g_sdst[node * 4 + 0];
    float sdst1 = g_sdst[node * 4 + 1];
    float sdst2 = g_sdst[node * 4 + 2];
    float sdst3 = g_sdst[node * 4 + 3];

    // ---- pass 1: per-head max of leaky_relu(logit) ----
    float mx0 = -1e30f, mx1 = -1e30f, mx2 = -1e30f, mx3 = -1e30f;
    for (int i = start + lane; i < end; i += 32) {
        unsigned p = g_csr_packed[i];
        int src = p >> 6;
        int ty = p & 63;
        const float* ss = &g_ssrc[src * 4];
        const float* rl = &g_rel_logit[ty * 4];
        float l0 = ss[0] + sdst0 + rl[0]; l0 = l0 > 0.f ? l0 : NEG_SLOPE * l0;
        float l1 = ss[1] + sdst1 + rl[1]; l1 = l1 > 0.f ? l1 : NEG_SLOPE * l1;
        float l2 = ss[2] + sdst2 + rl[2]; l2 = l2 > 0.f ? l2 : NEG_SLOPE * l2;
        float l3 = ss[3] + sdst3 + rl[3]; l3 = l3 > 0.f ? l3 : NEG_SLOPE * l3;
        mx0 = fmaxf(mx0, l0); mx1 = fmaxf(mx1, l1);
        mx2 = fmaxf(mx2, l2); mx3 = fmaxf(mx3, l3);
    }
#pragma unroll
    for (int o = 16; o; o >>= 1) {
        mx0 = fmaxf(mx0, __shfl_xor_sync(0xFFFFFFFFu, mx0, o));
        mx1 = fmaxf(mx1, __shfl_xor_sync(0xFFFFFFFFu, mx1, o));
        mx2 = fmaxf(mx2, __shfl_xor_sync(0xFFFFFFFFu, mx2, o));
        mx3 = fmaxf(mx3, __shfl_xor_sync(0xFFFFFFFFu, mx3, o));
    }

    // ---- pass 2: per-head sum of exp ----
    float sm0 = 0.f, sm1 = 0.f, sm2 = 0.f, sm3 = 0.f;
    for (int i = start + lane; i < end; i += 32) {
        unsigned p = g_csr_packed[i];
        int src = p >> 6;
        int ty = p & 63;
        const float* ss = &g_ssrc[src * 4];
        const float* rl = &g_rel_logit[ty * 4];
        float l0 = ss[0] + sdst0 + rl[0]; l0 = l0 > 0.f ? l0 : NEG_SLOPE * l0;
        float l1 = ss[1] + sdst1 + rl[1]; l1 = l1 > 0.f ? l1 : NEG_SLOPE * l1;
        float l2 = ss[2] + sdst2 + rl[2]; l2 = l2 > 0.f ? l2 : NEG_SLOPE * l2;
        float l3 = ss[3] + sdst3 + rl[3]; l3 = l3 > 0.f ? l3 : NEG_SLOPE * l3;
        sm0 += __expf(l0 - mx0); sm1 += __expf(l1 - mx1);
        sm2 += __expf(l2 - mx2); sm3 += __expf(l3 - mx3);
    }
#pragma unroll
    for (int o = 16; o; o >>= 1) {
        sm0 += __shfl_xor_sync(0xFFFFFFFFu, sm0, o);
        sm1 += __shfl_xor_sync(0xFFFFFFFFu, sm1, o);
        sm2 += __shfl_xor_sync(0xFFFFFFFFu, sm2, o);
        sm3 += __shfl_xor_sync(0xFFFFFFFFu, sm3, o);
    }
    float inv0 = (end > start) ? 1.0f / sm0 : 0.0f;
    float inv1 = (end > start) ? 1.0f / sm1 : 0.0f;
    float inv2 = (end > start) ? 1.0f / sm2 : 0.0f;
    float inv3 = (end > start) ? 1.0f / sm3 : 0.0f;

    // ---- pass 3: alpha + message accumulation, chunks of 32 edges ----
    int d0 = lane, d1 = lane + 32, d2 = lane + 64;
    int h0 = d0 / DHEAD, h1 = d1 / DHEAD, h2 = d2 / DHEAD;
    float acc0 = 0.f, acc1 = 0.f, acc2 = 0.f;

    for (int base = start; base < end; base += 32) {
        int i = base + lane;
        if (i < end) {
            unsigned p = g_csr_packed[i];
            int src = p >> 6;
            int ty = p & 63;
            const float* ss = &g_ssrc[src * 4];
            const float* rl = &g_rel_logit[ty * 4];
            float l0 = ss[0] + sdst0 + rl[0]; l0 = l0 > 0.f ? l0 : NEG_SLOPE * l0;
            float l1 = ss[1] + sdst1 + rl[1]; l1 = l1 > 0.f ? l1 : NEG_SLOPE * l1;
            float l2 = ss[2] + sdst2 + rl[2]; l2 = l2 > 0.f ? l2 : NEG_SLOPE * l2;
            float l3 = ss[3] + sdst3 + rl[3]; l3 = l3 > 0.f ? l3 : NEG_SLOPE * l3;
            float a0 = __expf(l0 - mx0) * inv0;
            float a1 = __expf(l1 - mx1) * inv1;
            float a2 = __expf(l2 - mx2) * inv2;
            float a3 = __expf(l3 - mx3) * inv3;
            sh_alpha[wslot][lane][0] = a0;
            sh_alpha[wslot][lane][1] = a1;
            sh_alpha[wslot][lane][2] = a2;
            sh_alpha[wslot][lane][3] = a3;
            sh_p[wslot][lane] = p;
            if (alpha_out) {
                float4 av = make_float4(a0, a1, a2, a3);
                reinterpret_cast<float4*>(alpha_out)[g_csr_eid[i]] = av;
            }
        }
        __syncwarp();
        int cnt = min(32, end - base);
        for (int j = 0; j < cnt; j++) {
            unsigned p = sh_p[wslot][j];
            int src = p >> 6;
            int ty = p & 63;
            const float* hs = &g_h[src * HID];
            const float* rr = &rel_emb[ty * HID];
            acc0 = fmaf(sh_alpha[wslot][j][h0], hs[d0] + rr[d0], acc0);
            acc1 = fmaf(sh_alpha[wslot][j][h1], hs[d1] + rr[d1], acc1);
            acc2 = fmaf(sh_alpha[wslot][j][h2], hs[d2] + rr[d2], acc2);
        }
        __syncwarp();
    }

    float* orow = out + node * HID;
    orow[d0] = gelu_tanh(acc0 + bias[d0]);
    orow[d1] = gelu_tanh(acc1 + bias[d1]);
    orow[d2] = gelu_tanh(acc2 + bias[d2]);
}

extern "C" void kernel_launch(void* const* d_in, const int* in_sizes, int n_in,
                              void* d_out, int out_size) {
    const float* x    = (const float*)d_in[0];
    const int*   ei   = (const int*)d_in[1];   // [2, E]
    const int*   et   = (const int*)d_in[2];   // [E]
    const float* W    = (const float*)d_in[3];
    const float* rel  = (const float*)d_in[4];
    const float* asrc = (const float*)d_in[5];
    const float* adst = (const float*)d_in[6];
    const float* arel = (const float*)d_in[7];
    const float* bias = (const float*)d_in[8];

    int n = in_sizes[0] / HID;
    int e = in_sizes[2];
    int r = in_sizes[4] / HID;
    if (n > NMAX) n = NMAX;
    if (e > EMAX) e = EMAX;

    float* out = (float*)d_out;
    float* alpha_out = (out_size >= n * HID + e * HEADS) ? (out + (size_t)n * HID)
                                                         : nullptr;

    k_gemm<<<(n * HID + 255) / 256, 256>>>(x, W, n);
    k_nodescore<<<(n * HEADS + 255) / 256, 256>>>(asrc, adst, n);
    k_rel<<<(r * HEADS + 255) / 256, 256>>>(rel, arel, r);
    k_zero<<<(n + 255) / 256, 256>>>(n);
    k_count<<<(e + 255) / 256, 256>>>(ei, e);
    k_scan<<<1, 1024>>>(n);
    k_fill<<<(e + 255) / 256, 256>>>(ei, et, e);
    k_agg<<<(n + 7) / 8, 256>>>(rel, bias, out, alpha_out, n);
}

// round 13
// speedup vs baseline: 1.0048x; 1.0048x over previous
#include <cuda_runtime.h>
#include <math.h>

#define NMAX 50000
#define EMAX 800000
#define HID 96
#define HEADS 4
#define DHEAD 24
#define RMAX 64
#define NEG_SLOPE 0.2f

// ---- device scratch (no allocations allowed) ----
__device__ float    g_h[NMAX * HID];          // x @ W
__device__ float    g_ssrc[NMAX * HEADS];     // per-node src attention scalar
__device__ float    g_sdst[NMAX * HEADS];     // per-node dst attention scalar
__device__ float    g_rel_logit[RMAX * HEADS];
__device__ int      g_cnt[NMAX];
__device__ int      g_off[NMAX + 1];
__device__ int      g_cur[NMAX];
__device__ unsigned g_csr_packed[EMAX];       // (src<<6) | type
__device__ int      g_csr_eid[EMAX];

__device__ __forceinline__ float gelu_tanh(float v) {
    float c = v + 0.044715f * v * v * v;
    return 0.5f * v * (1.0f + tanhf(0.7978845608028654f * c));
}

// ---- 1. h = x @ W  (warp covers one node, 32 consecutive output cols) ----
__global__ void k_gemm(const float* __restrict__ x, const float* __restrict__ W, int n) {
    int t = blockIdx.x * blockDim.x + threadIdx.x;
    if (t >= n * HID) return;
    int node = t / HID;
    int j = t - node * HID;
    const float* xr = x + node * HID;
    float acc = 0.0f;
#pragma unroll 8
    for (int k = 0; k < HID; k++)
        acc = fmaf(xr[k], W[k * HID + j], acc);
    g_h[t] = acc;
}

// ---- 2. per-node attention scalars ----
__global__ void k_nodescore(const float* __restrict__ att_src,
                            const float* __restrict__ att_dst, int n) {
    int t = blockIdx.x * blockDim.x + threadIdx.x;
    if (t >= n * HEADS) return;
    int node = t / HEADS;
    int h = t - node * HEADS;
    const float* hr = g_h + node * HID + h * DHEAD;
    float s1 = 0.0f, s2 = 0.0f;
#pragma unroll
    for (int d = 0; d < DHEAD; d++) {
        float v = hr[d];
        s1 = fmaf(v, att_src[h * DHEAD + d], s1);
        s2 = fmaf(v, att_dst[h * DHEAD + d], s2);
    }
    g_ssrc[t] = s1;
    g_sdst[t] = s2;
}

// ---- 3. per-relation attention scalars ----
__global__ void k_rel(const float* __restrict__ rel_emb,
                      const float* __restrict__ att_rel, int r) {
    int t = blockIdx.x * blockDim.x + threadIdx.x;
    if (t >= r * HEADS) return;
    int rr = t / HEADS;
    int h = t - rr * HEADS;
    float s = 0.0f;
#pragma unroll
    for (int d = 0; d < DHEAD; d++)
        s = fmaf(rel_emb[rr * HID + h * DHEAD + d], att_rel[h * DHEAD + d], s);
    g_rel_logit[t] = s;
}

// ---- 4. CSR build ----
__global__ void k_zero(int n) {
    int t = blockIdx.x * blockDim.x + threadIdx.x;
    if (t < n) g_cnt[t] = 0;
}

__global__ void k_count(const int* __restrict__ ei, int e) {
    int t = blockIdx.x * blockDim.x + threadIdx.x;
    if (t < e) atomicAdd(&g_cnt[ei[e + t]], 1);
}

// single-block exclusive scan over g_cnt -> g_off, g_cur; g_off[n] = total
__global__ void k_scan(int n) {
    __shared__ int warp_sums[32];
    __shared__ int s_carry;
    int tid = threadIdx.x, lane = tid & 31, wid = tid >> 5;
    if (tid == 0) s_carry = 0;
    __syncthreads();
    int nch = (n + 1023) / 1024;
    for (int c = 0; c < nch; c++) {
        int i = c * 1024 + tid;
        int v = (i < n) ? g_cnt[i] : 0;
        int xv = v;
#pragma unroll
        for (int o = 1; o < 32; o <<= 1) {
            int y = __shfl_up_sync(0xFFFFFFFFu, xv, o);
            if (lane >= o) xv += y;
        }
        if (lane == 31) warp_sums[wid] = xv;
        __syncthreads();
        if (wid == 0) {
            int w = warp_sums[lane];
#pragma unroll
            for (int o = 1; o < 32; o <<= 1) {
                int y = __shfl_up_sync(0xFFFFFFFFu, w, o);
                if (lane >= o) w += y;
            }
            warp_sums[lane] = w;
        }
        __syncthreads();
        int wprev = (wid > 0) ? warp_sums[wid - 1] : 0;
        int incl = xv + wprev;
        int carry = s_carry;
        if (i < n) {
            int ex = carry + incl - v;
            g_off[i] = ex;
            g_cur[i] = ex;
        }
        __syncthreads();
        if (tid == 1023) s_carry = carry + incl;
        __syncthreads();
    }
    if (tid == 0) g_off[n] = s_carry;
}

__global__ void k_fill(const int* __restrict__ ei, const int* __restrict__ et, int e) {
    int t = blockIdx.x * blockDim.x + threadIdx.x;
    if (t >= e) return;
    int src = ei[t];
    int dst = ei[e + t];
    int ty = et[t];
    int pos = atomicAdd(&g_cur[dst], 1);
    g_csr_packed[pos] = ((unsigned)src << 6) | (unsigned)ty;
    g_csr_eid[pos] = t;
}

// ---- 5. warp-per-node: segment softmax + weighted message aggregation ----
__global__ void __launch_bounds__(256) k_agg(const float* __restrict__ rel_emb,
                                             const float* __restrict__ bias,
                                             float* __restrict__ out,
                                             float* __restrict__ alpha_out, int n) {
    __shared__ float    sh_alpha[8][32][HEADS];
    __shared__ unsigned sh_p[8][32];
    int wslot = threadIdx.x >> 5;
    int lane = threadIdx.x & 31;
    int node = blockIdx.x * 8 + wslot;
    if (node >= n) return;

    int start = g_off[node];
    int end = g_off[node + 1];

    float sdst0 = g_sdst[node * 4 + 0];
    float sdst1 = g_sdst[node * 4 + 1];
    float sdst2 = g_sdst[node * 4 + 2];
    float sdst3 = g_sdst[node * 4 + 3];

    // ---- pass 1: per-head max of leaky_relu(logit) ----
    float mx0 = -1e30f, mx1 = -1e30f, mx2 = -1e30f, mx3 = -1e30f;
    for (int i = start + lane; i < end; i += 32) {
        unsigned p = g_csr_packed[i];
        int src = p >> 6;
        int ty = p & 63;
        const float* ss = &g_ssrc[src * 4];
        const float* rl = &g_rel_logit[ty * 4];
        float l0 = ss[0] + sdst0 + rl[0]; l0 = l0 > 0.f ? l0 : NEG_SLOPE * l0;
        float l1 = ss[1] + sdst1 + rl[1]; l1 = l1 > 0.f ? l1 : NEG_SLOPE * l1;
        float l2 = ss[2] + sdst2 + rl[2]; l2 = l2 > 0.f ? l2 : NEG_SLOPE * l2;
        float l3 = ss[3] + sdst3 + rl[3]; l3 = l3 > 0.f ? l3 : NEG_SLOPE * l3;
        mx0 = fmaxf(mx0, l0); mx1 = fmaxf(mx1, l1);
        mx2 = fmaxf(mx2, l2); mx3 = fmaxf(mx3, l3);
    }
#pragma unroll
    for (int o = 16; o; o >>= 1) {
        mx0 = fmaxf(mx0, __shfl_xor_sync(0xFFFFFFFFu, mx0, o));
        mx1 = fmaxf(mx1, __shfl_xor_sync(0xFFFFFFFFu, mx1, o));
        mx2 = fmaxf(mx2, __shfl_xor_sync(0xFFFFFFFFu, mx2, o));
        mx3 = fmaxf(mx3, __shfl_xor_sync(0xFFFFFFFFu, mx3, o));
    }

    // ---- pass 2: per-head sum of exp ----
    float sm0 = 0.f, sm1 = 0.f, sm2 = 0.f, sm3 = 0.f;
    for (int i = start + lane; i < end; i += 32) {
        unsigned p = g_csr_packed[i];
        int src = p >> 6;
        int ty = p & 63;
        const float* ss = &g_ssrc[src * 4];
        const float* rl = &g_rel_logit[ty * 4];
        float l0 = ss[0] + sdst0 + rl[0]; l0 = l0 > 0.f ? l0 : NEG_SLOPE * l0;
        float l1 = ss[1] + sdst1 + rl[1]; l1 = l1 > 0.f ? l1 : NEG_SLOPE * l1;
        float l2 = ss[2] + sdst2 + rl[2]; l2 = l2 > 0.f ? l2 : NEG_SLOPE * l2;
        float l3 = ss[3] + sdst3 + rl[3]; l3 = l3 > 0.f ? l3 : NEG_SLOPE * l3;
        sm0 += __expf(l0 - mx0); sm1 += __expf(l1 - mx1);
        sm2 += __expf(l2 - mx2); sm3 += __expf(l3 - mx3);
    }
#pragma unroll
    for (int o = 16; o; o >>= 1) {
        sm0 += __shfl_xor_sync(0xFFFFFFFFu, sm0, o);
        sm1 += __shfl_xor_sync(0xFFFFFFFFu, sm1, o);
        sm2 += __shfl_xor_sync(0xFFFFFFFFu, sm2, o);
        sm3 += __shfl_xor_sync(0xFFFFFFFFu, sm3, o);
    }
    float inv0 = (end > start) ? 1.0f / sm0 : 0.0f;
    float inv1 = (end > start) ? 1.0f / sm1 : 0.0f;
    float inv2 = (end > start) ? 1.0f / sm2 : 0.0f;
    float inv3 = (end > start) ? 1.0f / sm3 : 0.0f;

    // ---- pass 3: alpha + message accumulation, chunks of 32 edges ----
    int d0 = lane, d1 = lane + 32, d2 = lane + 64;
    int h0 = d0 / DHEAD, h1 = d1 / DHEAD, h2 = d2 / DHEAD;
    float acc0 = 0.f, acc1 = 0.f, acc2 = 0.f;

    for (int base = start; base < end; base += 32) {
        int i = base + lane;
        if (i < end) {
            unsigned p = g_csr_packed[i];
            int src = p >> 6;
            int ty = p & 63;
            const float* ss = &g_ssrc[src * 4];
            const float* rl = &g_rel_logit[ty * 4];
            float l0 = ss[0] + sdst0 + rl[0]; l0 = l0 > 0.f ? l0 : NEG_SLOPE * l0;
            float l1 = ss[1] + sdst1 + rl[1]; l1 = l1 > 0.f ? l1 : NEG_SLOPE * l1;
            float l2 = ss[2] + sdst2 + rl[2]; l2 = l2 > 0.f ? l2 : NEG_SLOPE * l2;
            float l3 = ss[3] + sdst3 + rl[3]; l3 = l3 > 0.f ? l3 : NEG_SLOPE * l3;
            float a0 = __expf(l0 - mx0) * inv0;
            float a1 = __expf(l1 - mx1) * inv1;
            float a2 = __expf(l2 - mx2) * inv2;
            float a3 = __expf(l3 - mx3) * inv3;
            sh_alpha[wslot][lane][0] = a0;
            sh_alpha[wslot][lane][1] = a1;
            sh_alpha[wslot][lane][2] = a2;
            sh_alpha[wslot][lane][3] = a3;
            sh_p[wslot][lane] = p;
            if (alpha_out) {
                float4 av = make_float4(a0, a1, a2, a3);
                reinterpret_cast<float4*>(alpha_out)[g_csr_eid[i]] = av;
            }
        }
        __syncwarp();
        int cnt = min(32, end - base);
        for (int j = 0; j < cnt; j++) {
            unsigned p = sh_p[wslot][j];
            int src = p >> 6;
            int ty = p & 63;
            const float* hs = &g_h[src * HID];
            const float* rr = &rel_emb[ty * HID];
            acc0 = fmaf(sh_alpha[wslot][j][h0], hs[d0] + rr[d0], acc0);
            acc1 = fmaf(sh_alpha[wslot][j][h1], hs[d1] + rr[d1], acc1);
            acc2 = fmaf(sh_alpha[wslot][j][h2], hs[d2] + rr[d2], acc2);
        }
        __syncwarp();
    }

    float* orow = out + node * HID;
    orow[d0] = gelu_tanh(acc0 + bias[d0]);
    orow[d1] = gelu_tanh(acc1 + bias[d1]);
    orow[d2] = gelu_tanh(acc2 + bias[d2]);
}

extern "C" void kernel_launch(void* const* d_in, const int* in_sizes, int n_in,
                              void* d_out, int out_size) {
    const float* x    = (const float*)d_in[0];
    const int*   ei   = (const int*)d_in[1];   // [2, E]
    const int*   et   = (const int*)d_in[2];   // [E]
    const float* W    = (const float*)d_in[3];
    const float* rel  = (const float*)d_in[4];
    const float* asrc = (const float*)d_in[5];
    const float* adst = (const float*)d_in[6];
    const float* arel = (const float*)d_in[7];
    const float* bias = (const float*)d_in[8];

    int n = in_sizes[0] / HID;
    int e = in_sizes[2];
    int r = in_sizes[4] / HID;
    if (n > NMAX) n = NMAX;
    if (e > EMAX) e = EMAX;

    float* out = (float*)d_out;
    float* alpha_out = (out_size >= n * HID + e * HEADS) ? (out + (size_t)n * HID)
                                                         : nullptr;

    k_gemm<<<(n * HID + 255) / 256, 256>>>(x, W, n);
    k_nodescore<<<(n * HEADS + 255) / 256, 256>>>(asrc, adst, n);
    k_rel<<<(r * HEADS + 255) / 256, 256>>>(rel, arel, r);
    k_zero<<<(n + 255) / 256, 256>>>(n);
    k_count<<<(e + 255) / 256, 256>>>(ei, e);
    k_scan<<<1, 1024>>>(n);
    k_fill<<<(e + 255) / 256, 256>>>(ei, et, e);
    k_agg<<<(n + 7) / 8, 256>>>(rel, bias, out, alpha_out, n);
}

// round 14
// speedup vs baseline: 1.7224x; 1.7142x over previous
#include <cuda_runtime.h>
#include <math.h>

#define NMAX 50000
#define EMAX 800000
#define HID 96
#define HEADS 4
#define DHEAD 24
#define RMAX 64
#define NEG_SLOPE 0.2f
#define SCAN_CHUNK 1024

typedef unsigned long long ull;

// ---- device scratch (no allocations allowed) ----
__device__ float    g_h[NMAX * HID];          // x @ W
__device__ float    g_ssrc[NMAX * HEADS];     // per-node src attention scalar
__device__ float    g_sdst[NMAX * HEADS];     // per-node dst attention scalar
__device__ float    g_rel_logit[RMAX * HEADS];
__device__ int      g_cnt[NMAX];
__device__ int      g_off[NMAX + 1];
__device__ int      g_cur[NMAX];
__device__ int      g_bsum[64];
__device__ unsigned g_csr_packed[EMAX];       // (src<<6) | type
__device__ int      g_csr_eid[EMAX];
__device__ float4   g_elogit[EMAX];           // per-edge post-leaky logits (CSR order)

__device__ __forceinline__ float gelu_tanh(float v) {
    float c = v + 0.044715f * v * v * v;
    return 0.5f * v * (1.0f + tanhf(0.7978845608028654f * c));
}

__device__ __forceinline__ void fma2(ull& d, ull a, ull b) {
    asm volatile("fma.rn.f32x2 %0, %1, %2, %0;" : "+l"(d) : "l"(a), "l"(b));
}
__device__ __forceinline__ ull pack2(float v) {
    ull r;
    unsigned u = __float_as_uint(v);
    asm("mov.b64 %0, {%1, %1};" : "=l"(r) : "r"(u));
    return r;
}

// ---- 1. h = x @ W  -- register-blocked: thread = 4 nodes x 8 cols, f32x2 FMA ----
// block = 96 threads: cp = tid%12 (cols 8cp..8cp+7), r = tid/12 (0..7)
// nodes handled: nb + r + 8*i, i = 0..3   (32 nodes per block)
__global__ void __launch_bounds__(96) k_gemm(const float* __restrict__ x,
                                             const float* __restrict__ W, int n) {
    int cp = threadIdx.x % 12;
    int r  = threadIdx.x / 12;
    int nb = blockIdx.x * 32;

    int nd[4];
    const float* xr[4];
#pragma unroll
    for (int i = 0; i < 4; i++) {
        int node = nb + r + 8 * i;
        nd[i] = node;
        int cnode = node < n ? node : (n - 1);
        xr[i] = x + (size_t)cnode * HID;
    }

    ull acc[4][4];
#pragma unroll
    for (int i = 0; i < 4; i++)
#pragma unroll
        for (int c = 0; c < 4; c++) acc[i][c] = 0ULL;

    const ulonglong2* W2 = (const ulonglong2*)W;  // row k = 24 ulonglong2

    for (int k0 = 0; k0 < HID; k0 += 4) {
        float4 xv[4];
#pragma unroll
        for (int i = 0; i < 4; i++)
            xv[i] = *(const float4*)(xr[i] + k0);
#pragma unroll
        for (int kk = 0; kk < 4; kk++) {
            int k = k0 + kk;
            ulonglong2 wa = W2[k * 24 + cp * 2];
            ulonglong2 wb = W2[k * 24 + cp * 2 + 1];
#pragma unroll
            for (int i = 0; i < 4; i++) {
                float xs = (kk == 0) ? xv[i].x : (kk == 1) ? xv[i].y
                          : (kk == 2) ? xv[i].z : xv[i].w;
                ull xp = pack2(xs);
                fma2(acc[i][0], xp, wa.x);
                fma2(acc[i][1], xp, wa.y);
                fma2(acc[i][2], xp, wb.x);
                fma2(acc[i][3], xp, wb.y);
            }
        }
    }

#pragma unroll
    for (int i = 0; i < 4; i++) {
        if (nd[i] < n) {
            float* o = g_h + (size_t)nd[i] * HID + cp * 8;
            ulonglong2 s0, s1;
            s0.x = acc[i][0]; s0.y = acc[i][1];
            s1.x = acc[i][2]; s1.y = acc[i][3];
            *(ulonglong2*)(o)     = s0;
            *(ulonglong2*)(o + 4) = s1;
        }
    }
}

// ---- 2. per-node attention scalars (float4) ----
__global__ void k_nodescore(const float* __restrict__ att_src,
                            const float* __restrict__ att_dst, int n) {
    int t = blockIdx.x * blockDim.x + threadIdx.x;
    if (t >= n * HEADS) return;
    int node = t >> 2;
    int h = t & 3;
    const float4* hr = (const float4*)(g_h + (size_t)node * HID + h * DHEAD);
    const float4* as = (const float4*)(att_src + h * DHEAD);
    const float4* ad = (const float4*)(att_dst + h * DHEAD);
    float s1 = 0.0f, s2 = 0.0f;
#pragma unroll
    for (int i = 0; i < 6; i++) {
        float4 hv = hr[i], av = as[i], dv = ad[i];
        s1 = fmaf(hv.x, av.x, fmaf(hv.y, av.y, fmaf(hv.z, av.z, fmaf(hv.w, av.w, s1))));
        s2 = fmaf(hv.x, dv.x, fmaf(hv.y, dv.y, fmaf(hv.z, dv.z, fmaf(hv.w, dv.w, s2))));
    }
    g_ssrc[t] = s1;
    g_sdst[t] = s2;
}

// ---- 3. per-relation attention scalars ----
__global__ void k_rel(const float* __restrict__ rel_emb,
                      const float* __restrict__ att_rel, int r) {
    int t = blockIdx.x * blockDim.x + threadIdx.x;
    if (t >= r * HEADS) return;
    int rr = t / HEADS;
    int h = t - rr * HEADS;
    float s = 0.0f;
#pragma unroll
    for (int d = 0; d < DHEAD; d++)
        s = fmaf(rel_emb[rr * HID + h * DHEAD + d], att_rel[h * DHEAD + d], s);
    g_rel_logit[t] = s;
}

// ---- 4. CSR build ----
__global__ void k_zero(int n) {
    int t = blockIdx.x * blockDim.x + threadIdx.x;
    if (t < n) g_cnt[t] = 0;
}

__global__ void k_count(const int* __restrict__ ei, int e) {
    int t = blockIdx.x * blockDim.x + threadIdx.x;
    if (t < e) atomicAdd(&g_cnt[ei[e + t]], 1);
}

// multi-block scan, stage 1: per-block local exclusive scan + block total
__global__ void __launch_bounds__(SCAN_CHUNK) k_scan1(int n) {
    __shared__ int ws[32];
    int tid = threadIdx.x, lane = tid & 31, wid = tid >> 5;
    int i = blockIdx.x * SCAN_CHUNK + tid;
    int v = (i < n) ? g_cnt[i] : 0;
    int xv = v;
#pragma unroll
    for (int o = 1; o < 32; o <<= 1) {
        int y = __shfl_up_sync(0xFFFFFFFFu, xv, o);
        if (lane >= o) xv += y;
    }
    if (lane == 31) ws[wid] = xv;
    __syncthreads();
    if (wid == 0) {
        int w = ws[lane];
#pragma unroll
        for (int o = 1; o < 32; o <<= 1) {
            int y = __shfl_up_sync(0xFFFFFFFFu, w, o);
            if (lane >= o) w += y;
        }
        ws[lane] = w;
    }
    __syncthreads();
    int incl = xv + (wid ? ws[wid - 1] : 0);
    if (i < n) g_off[i] = incl - v;                 // local exclusive
    if (tid == SCAN_CHUNK - 1) g_bsum[blockIdx.x] = incl;  // block total
}

// stage 2: single block, 64 threads: exclusive scan of block totals; write grand total
__global__ void k_scan2(int nb, int n) {
    __shared__ int tot0;
    int tid = threadIdx.x, lane = tid & 31, wid = tid >> 5;
    int v = (tid < nb) ? g_bsum[tid] : 0;
    int xv = v;
#pragma unroll
    for (int o = 1; o < 32; o <<= 1) {
        int y = __shfl_up_sync(0xFFFFFFFFu, xv, o);
        if (lane >= o) xv += y;
    }
    if (wid == 0 && lane == 31) tot0 = xv;
    __syncthreads();
    int excl = xv - v + (wid ? tot0 : 0);
    if (tid < nb) g_bsum[tid] = excl;
    if (tid == 63) g_off[n] = xv + tot0;   // warp1 inclusive tail + warp0 total
}

// stage 3: add block bases, init g_cur
__global__ void __launch_bounds__(SCAN_CHUNK) k_scan3(int n) {
    int i = blockIdx.x * SCAN_CHUNK + threadIdx.x;
    if (i < n) {
        int o = g_off[i] + g_bsum[blockIdx.x];
        g_off[i] = o;
        g_cur[i] = o;
    }
}

// fill CSR + precompute per-edge post-leaky logits (all 4 heads)
__global__ void k_fill(const int* __restrict__ ei, const int* __restrict__ et, int e) {
    int t = blockIdx.x * blockDim.x + threadIdx.x;
    if (t >= e) return;
    int src = ei[t];
    int dst = ei[e + t];
    int ty = et[t];
    int pos = atomicAdd(&g_cur[dst], 1);
    g_csr_packed[pos] = ((unsigned)src << 6) | (unsigned)ty;
    g_csr_eid[pos] = t;
    float4 ss = *(const float4*)&g_ssrc[src * 4];
    float4 sd = *(const float4*)&g_sdst[dst * 4];
    float4 rl = *(const float4*)&g_rel_logit[ty * 4];
    float l0 = ss.x + sd.x + rl.x; l0 = l0 > 0.f ? l0 : NEG_SLOPE * l0;
    float l1 = ss.y + sd.y + rl.y; l1 = l1 > 0.f ? l1 : NEG_SLOPE * l1;
    float l2 = ss.z + sd.z + rl.z; l2 = l2 > 0.f ? l2 : NEG_SLOPE * l2;
    float l3 = ss.w + sd.w + rl.w; l3 = l3 > 0.f ? l3 : NEG_SLOPE * l3;
    g_elogit[pos] = make_float4(l0, l1, l2, l3);
}

// ---- 5. warp-per-node: segment softmax + weighted message aggregation ----
__global__ void __launch_bounds__(256) k_agg(const float* __restrict__ rel_emb,
                                             const float* __restrict__ bias,
                                             float* __restrict__ out,
                                             float* __restrict__ alpha_out, int n) {
    __shared__ float    sh_alpha[8][32][HEADS];
    __shared__ unsigned sh_p[8][32];
    int wslot = threadIdx.x >> 5;
    int lane = threadIdx.x & 31;
    int node = blockIdx.x * 8 + wslot;
    if (node >= n) return;

    int start = g_off[node];
    int end = g_off[node + 1];

    // ---- pass 1: per-head max (streaming precomputed logits) ----
    float mx0 = -1e30f, mx1 = -1e30f, mx2 = -1e30f, mx3 = -1e30f;
    for (int i = start + lane; i < end; i += 32) {
        float4 L = g_elogit[i];
        mx0 = fmaxf(mx0, L.x); mx1 = fmaxf(mx1, L.y);
        mx2 = fmaxf(mx2, L.z); mx3 = fmaxf(mx3, L.w);
    }
#pragma unroll
    for (int o = 16; o; o >>= 1) {
        mx0 = fmaxf(mx0, __shfl_xor_sync(0xFFFFFFFFu, mx0, o));
        mx1 = fmaxf(mx1, __shfl_xor_sync(0xFFFFFFFFu, mx1, o));
        mx2 = fmaxf(mx2, __shfl_xor_sync(0xFFFFFFFFu, mx2, o));
        mx3 = fmaxf(mx3, __shfl_xor_sync(0xFFFFFFFFu, mx3, o));
    }

    // ---- pass 2: per-head sum of exp ----
    float sm0 = 0.f, sm1 = 0.f, sm2 = 0.f, sm3 = 0.f;
    for (int i = start + lane; i < end; i += 32) {
        float4 L = g_elogit[i];
        sm0 += __expf(L.x - mx0); sm1 += __expf(L.y - mx1);
        sm2 += __expf(L.z - mx2); sm3 += __expf(L.w - mx3);
    }
#pragma unroll
    for (int o = 16; o; o >>= 1) {
        sm0 += __shfl_xor_sync(0xFFFFFFFFu, sm0, o);
        sm1 += __shfl_xor_sync(0xFFFFFFFFu, sm1, o);
        sm2 += __shfl_xor_sync(0xFFFFFFFFu, sm2, o);
        sm3 += __shfl_xor_sync(0xFFFFFFFFu, sm3, o);
    }
    float inv0 = (end > start) ? 1.0f / sm0 : 0.0f;
    float inv1 = (end > start) ? 1.0f / sm1 : 0.0f;
    float inv2 = (end > start) ? 1.0f / sm2 : 0.0f;
    float inv3 = (end > start) ? 1.0f / sm3 : 0.0f;

    // ---- pass 3: alpha + message accumulation, chunks of 32 edges ----
    int d0 = lane, d1 = lane + 32, d2 = lane + 64;
    int h0 = d0 / DHEAD, h1 = d1 / DHEAD, h2 = d2 / DHEAD;
    float acc0 = 0.f, acc1 = 0.f, acc2 = 0.f;

    for (int base = start; base < end; base += 32) {
        int i = base + lane;
        if (i < end) {
            float4 L = g_elogit[i];
            float a0 = __expf(L.x - mx0) * inv0;
            float a1 = __expf(L.y - mx1) * inv1;
            float a2 = __expf(L.z - mx2) * inv2;
            float a3 = __expf(L.w - mx3) * inv3;
            sh_alpha[wslot][lane][0] = a0;
            sh_alpha[wslot][lane][1] = a1;
            sh_alpha[wslot][lane][2] = a2;
            sh_alpha[wslot][lane][3] = a3;
            sh_p[wslot][lane] = g_csr_packed[i];
            if (alpha_out) {
                reinterpret_cast<float4*>(alpha_out)[g_csr_eid[i]] =
                    make_float4(a0, a1, a2, a3);
            }
        }
        __syncwarp();
        int cnt = min(32, end - base);
        for (int j = 0; j < cnt; j++) {
            unsigned p = sh_p[wslot][j];
            int src = p >> 6;
            int ty = p & 63;
            const float* hs = &g_h[(size_t)src * HID];
            const float* rr = &rel_emb[ty * HID];
            acc0 = fmaf(sh_alpha[wslot][j][h0], hs[d0] + rr[d0], acc0);
            acc1 = fmaf(sh_alpha[wslot][j][h1], hs[d1] + rr[d1], acc1);
            acc2 = fmaf(sh_alpha[wslot][j][h2], hs[d2] + rr[d2], acc2);
        }
        __syncwarp();
    }

    float* orow = out + (size_t)node * HID;
    orow[d0] = gelu_tanh(acc0 + bias[d0]);
    orow[d1] = gelu_tanh(acc1 + bias[d1]);
    orow[d2] = gelu_tanh(acc2 + bias[d2]);
}

extern "C" void kernel_launch(void* const* d_in, const int* in_sizes, int n_in,
                              void* d_out, int out_size) {
    const float* x    = (const float*)d_in[0];
    const int*   ei   = (const int*)d_in[1];   // [2, E]
    const int*   et   = (const int*)d_in[2];   // [E]
    const float* W    = (const float*)d_in[3];
    const float* rel  = (const float*)d_in[4];
    const float* asrc = (const float*)d_in[5];
    const float* adst = (const float*)d_in[6];
    const float* arel = (const float*)d_in[7];
    const float* bias = (const float*)d_in[8];

    int n = in_sizes[0] / HID;
    int e = in_sizes[2];
    int r = in_sizes[4] / HID;
    if (n > NMAX) n = NMAX;
    if (e > EMAX) e = EMAX;

    float* out = (float*)d_out;
    float* alpha_out = (out_size >= n * HID + e * HEADS) ? (out + (size_t)n * HID)
                                                         : nullptr;

    int nscan = (n + SCAN_CHUNK - 1) / SCAN_CHUNK;

    k_gemm<<<(n + 31) / 32, 96>>>(x, W, n);
    k_nodescore<<<(n * HEADS + 255) / 256, 256>>>(asrc, adst, n);
    k_rel<<<(r * HEADS + 255) / 256, 256>>>(rel, arel, r);
    k_zero<<<(n + 255) / 256, 256>>>(n);
    k_count<<<(e + 255) / 256, 256>>>(ei, e);
    k_scan1<<<nscan, SCAN_CHUNK>>>(n);
    k_scan2<<<1, 64>>>(nscan, n);
    k_scan3<<<nscan, SCAN_CHUNK>>>(n);
    k_fill<<<(e + 255) / 256, 256>>>(ei, et, e);
    k_agg<<<(n + 7) / 8, 256>>>(rel, bias, out, alpha_out, n);
}

// round 15
// speedup vs baseline: 1.7227x; 1.0002x over previous
#include <cuda_runtime.h>
#include <math.h>

#define NMAX 50000
#define EMAX 800000
#define HID 96
#define HEADS 4
#define DHEAD 24
#define RMAX 64
#define NEG_SLOPE 0.2f
#define SCAN_CHUNK 1024

typedef unsigned long long ull;

// ---- device scratch (no allocations allowed) ----
__device__ float    g_h[NMAX * HID];          // x @ W
__device__ float    g_ssrc[NMAX * HEADS];     // per-node src attention scalar
__device__ float    g_sdst[NMAX * HEADS];     // per-node dst attention scalar
__device__ float    g_rel_logit[RMAX * HEADS];
__device__ int      g_cnt[NMAX];
__device__ int      g_off[NMAX + 1];
__device__ int      g_cur[NMAX];
__device__ int      g_bsum[64];
__device__ unsigned g_csr_packed[EMAX];       // (src<<6) | type
__device__ int      g_csr_eid[EMAX];
__device__ float4   g_elogit[EMAX];           // per-edge post-leaky logits (CSR order)

__device__ __forceinline__ float gelu_tanh(float v) {
    float c = v + 0.044715f * v * v * v;
    return 0.5f * v * (1.0f + tanhf(0.7978845608028654f * c));
}

__device__ __forceinline__ void fma2(ull& d, ull a, ull b) {
    asm volatile("fma.rn.f32x2 %0, %1, %2, %0;" : "+l"(d) : "l"(a), "l"(b));
}
__device__ __forceinline__ ull pack2(float v) {
    ull r;
    unsigned u = __float_as_uint(v);
    asm("mov.b64 %0, {%1, %1};" : "=l"(r) : "r"(u));
    return r;
}

// ---- 1. h = x @ W  -- register-blocked: thread = 4 nodes x 8 cols, f32x2 FMA ----
// block = 96 threads: cp = tid%12 (cols 8cp..8cp+7), r = tid/12 (0..7)
// nodes handled: nb + r + 8*i, i = 0..3   (32 nodes per block)
__global__ void __launch_bounds__(96) k_gemm(const float* __restrict__ x,
                                             const float* __restrict__ W, int n) {
    int cp = threadIdx.x % 12;
    int r  = threadIdx.x / 12;
    int nb = blockIdx.x * 32;

    int nd[4];
    const float* xr[4];
#pragma unroll
    for (int i = 0; i < 4; i++) {
        int node = nb + r + 8 * i;
        nd[i] = node;
        int cnode = node < n ? node : (n - 1);
        xr[i] = x + (size_t)cnode * HID;
    }

    ull acc[4][4];
#pragma unroll
    for (int i = 0; i < 4; i++)
#pragma unroll
        for (int c = 0; c < 4; c++) acc[i][c] = 0ULL;

    const ulonglong2* W2 = (const ulonglong2*)W;  // row k = 24 ulonglong2

    for (int k0 = 0; k0 < HID; k0 += 4) {
        float4 xv[4];
#pragma unroll
        for (int i = 0; i < 4; i++)
            xv[i] = *(const float4*)(xr[i] + k0);
#pragma unroll
        for (int kk = 0; kk < 4; kk++) {
            int k = k0 + kk;
            ulonglong2 wa = W2[k * 24 + cp * 2];
            ulonglong2 wb = W2[k * 24 + cp * 2 + 1];
#pragma unroll
            for (int i = 0; i < 4; i++) {
                float xs = (kk == 0) ? xv[i].x : (kk == 1) ? xv[i].y
                          : (kk == 2) ? xv[i].z : xv[i].w;
                ull xp = pack2(xs);
                fma2(acc[i][0], xp, wa.x);
                fma2(acc[i][1], xp, wa.y);
                fma2(acc[i][2], xp, wb.x);
                fma2(acc[i][3], xp, wb.y);
            }
        }
    }

#pragma unroll
    for (int i = 0; i < 4; i++) {
        if (nd[i] < n) {
            float* o = g_h + (size_t)nd[i] * HID + cp * 8;
            ulonglong2 s0, s1;
            s0.x = acc[i][0]; s0.y = acc[i][1];
            s1.x = acc[i][2]; s1.y = acc[i][3];
            *(ulonglong2*)(o)     = s0;
            *(ulonglong2*)(o + 4) = s1;
        }
    }
}

// ---- 2. per-node attention scalars (float4) ----
__global__ void k_nodescore(const float* __restrict__ att_src,
                            const float* __restrict__ att_dst, int n) {
    int t = blockIdx.x * blockDim.x + threadIdx.x;
    if (t >= n * HEADS) return;
    int node = t >> 2;
    int h = t & 3;
    const float4* hr = (const float4*)(g_h + (size_t)node * HID + h * DHEAD);
    const float4* as = (const float4*)(att_src + h * DHEAD);
    const float4* ad = (const float4*)(att_dst + h * DHEAD);
    float s1 = 0.0f, s2 = 0.0f;
#pragma unroll
    for (int i = 0; i < 6; i++) {
        float4 hv = hr[i], av = as[i], dv = ad[i];
        s1 = fmaf(hv.x, av.x, fmaf(hv.y, av.y, fmaf(hv.z, av.z, fmaf(hv.w, av.w, s1))));
        s2 = fmaf(hv.x, dv.x, fmaf(hv.y, dv.y, fmaf(hv.z, dv.z, fmaf(hv.w, dv.w, s2))));
    }
    g_ssrc[t] = s1;
    g_sdst[t] = s2;
}

// ---- 3. per-relation attention scalars ----
__global__ void k_rel(const float* __restrict__ rel_emb,
                      const float* __restrict__ att_rel, int r) {
    int t = blockIdx.x * blockDim.x + threadIdx.x;
    if (t >= r * HEADS) return;
    int rr = t / HEADS;
    int h = t - rr * HEADS;
    float s = 0.0f;
#pragma unroll
    for (int d = 0; d < DHEAD; d++)
        s = fmaf(rel_emb[rr * HID + h * DHEAD + d], att_rel[h * DHEAD + d], s);
    g_rel_logit[t] = s;
}

// ---- 4. CSR build ----
__global__ void k_zero(int n) {
    int t = blockIdx.x * blockDim.x + threadIdx.x;
    if (t < n) g_cnt[t] = 0;
}

__global__ void k_count(const int* __restrict__ ei, int e) {
    int t = blockIdx.x * blockDim.x + threadIdx.x;
    if (t < e) atomicAdd(&g_cnt[ei[e + t]], 1);
}

// multi-block scan, stage 1: per-block local exclusive scan + block total
__global__ void __launch_bounds__(SCAN_CHUNK) k_scan1(int n) {
    __shared__ int ws[32];
    int tid = threadIdx.x, lane = tid & 31, wid = tid >> 5;
    int i = blockIdx.x * SCAN_CHUNK + tid;
    int v = (i < n) ? g_cnt[i] : 0;
    int xv = v;
#pragma unroll
    for (int o = 1; o < 32; o <<= 1) {
        int y = __shfl_up_sync(0xFFFFFFFFu, xv, o);
        if (lane >= o) xv += y;
    }
    if (lane == 31) ws[wid] = xv;
    __syncthreads();
    if (wid == 0) {
        int w = ws[lane];
#pragma unroll
        for (int o = 1; o < 32; o <<= 1) {
            int y = __shfl_up_sync(0xFFFFFFFFu, w, o);
            if (lane >= o) w += y;
        }
        ws[lane] = w;
    }
    __syncthreads();
    int incl = xv + (wid ? ws[wid - 1] : 0);
    if (i < n) g_off[i] = incl - v;                 // local exclusive
    if (tid == SCAN_CHUNK - 1) g_bsum[blockIdx.x] = incl;  // block total
}

// stage 2: single block, 64 threads: exclusive scan of block totals; write grand total
__global__ void k_scan2(int nb, int n) {
    __shared__ int tot0;
    int tid = threadIdx.x, lane = tid & 31, wid = tid >> 5;
    int v = (tid < nb) ? g_bsum[tid] : 0;
    int xv = v;
#pragma unroll
    for (int o = 1; o < 32; o <<= 1) {
        int y = __shfl_up_sync(0xFFFFFFFFu, xv, o);
        if (lane >= o) xv += y;
    }
    if (wid == 0 && lane == 31) tot0 = xv;
    __syncthreads();
    int excl = xv - v + (wid ? tot0 : 0);
    if (tid < nb) g_bsum[tid] = excl;
    if (tid == 63) g_off[n] = xv + tot0;   // warp1 inclusive tail + warp0 total
}

// stage 3: add block bases, init g_cur
__global__ void __launch_bounds__(SCAN_CHUNK) k_scan3(int n) {
    int i = blockIdx.x * SCAN_CHUNK + threadIdx.x;
    if (i < n) {
        int o = g_off[i] + g_bsum[blockIdx.x];
        g_off[i] = o;
        g_cur[i] = o;
    }
}

// fill CSR + precompute per-edge post-leaky logits (all 4 heads)
__global__ void k_fill(const int* __restrict__ ei, const int* __restrict__ et, int e) {
    int t = blockIdx.x * blockDim.x + threadIdx.x;
    if (t >= e) return;
    int src = ei[t];
    int dst = ei[e + t];
    int ty = et[t];
    int pos = atomicAdd(&g_cur[dst], 1);
    g_csr_packed[pos] = ((unsigned)src << 6) | (unsigned)ty;
    g_csr_eid[pos] = t;
    float4 ss = *(const float4*)&g_ssrc[src * 4];
    float4 sd = *(const float4*)&g_sdst[dst * 4];
    float4 rl = *(const float4*)&g_rel_logit[ty * 4];
    float l0 = ss.x + sd.x + rl.x; l0 = l0 > 0.f ? l0 : NEG_SLOPE * l0;
    float l1 = ss.y + sd.y + rl.y; l1 = l1 > 0.f ? l1 : NEG_SLOPE * l1;
    float l2 = ss.z + sd.z + rl.z; l2 = l2 > 0.f ? l2 : NEG_SLOPE * l2;
    float l3 = ss.w + sd.w + rl.w; l3 = l3 > 0.f ? l3 : NEG_SLOPE * l3;
    g_elogit[pos] = make_float4(l0, l1, l2, l3);
}

// ---- 5. warp-per-node: segment softmax + weighted message aggregation ----
__global__ void __launch_bounds__(256) k_agg(const float* __restrict__ rel_emb,
                                             const float* __restrict__ bias,
                                             float* __restrict__ out,
                                             float* __restrict__ alpha_out, int n) {
    __shared__ float    sh_alpha[8][32][HEADS];
    __shared__ unsigned sh_p[8][32];
    int wslot = threadIdx.x >> 5;
    int lane = threadIdx.x & 31;
    int node = blockIdx.x * 8 + wslot;
    if (node >= n) return;

    int start = g_off[node];
    int end = g_off[node + 1];

    // ---- pass 1: per-head max (streaming precomputed logits) ----
    float mx0 = -1e30f, mx1 = -1e30f, mx2 = -1e30f, mx3 = -1e30f;
    for (int i = start + lane; i < end; i += 32) {
        float4 L = g_elogit[i];
        mx0 = fmaxf(mx0, L.x); mx1 = fmaxf(mx1, L.y);
        mx2 = fmaxf(mx2, L.z); mx3 = fmaxf(mx3, L.w);
    }
#pragma unroll
    for (int o = 16; o; o >>= 1) {
        mx0 = fmaxf(mx0, __shfl_xor_sync(0xFFFFFFFFu, mx0, o));
        mx1 = fmaxf(mx1, __shfl_xor_sync(0xFFFFFFFFu, mx1, o));
        mx2 = fmaxf(mx2, __shfl_xor_sync(0xFFFFFFFFu, mx2, o));
        mx3 = fmaxf(mx3, __shfl_xor_sync(0xFFFFFFFFu, mx3, o));
    }

    // ---- pass 2: per-head sum of exp ----
    float sm0 = 0.f, sm1 = 0.f, sm2 = 0.f, sm3 = 0.f;
    for (int i = start + lane; i < end; i += 32) {
        float4 L = g_elogit[i];
        sm0 += __expf(L.x - mx0); sm1 += __expf(L.y - mx1);
        sm2 += __expf(L.z - mx2); sm3 += __expf(L.w - mx3);
    }
#pragma unroll
    for (int o = 16; o; o >>= 1) {
        sm0 += __shfl_xor_sync(0xFFFFFFFFu, sm0, o);
        sm1 += __shfl_xor_sync(0xFFFFFFFFu, sm1, o);
        sm2 += __shfl_xor_sync(0xFFFFFFFFu, sm2, o);
        sm3 += __shfl_xor_sync(0xFFFFFFFFu, sm3, o);
    }
    float inv0 = (end > start) ? 1.0f / sm0 : 0.0f;
    float inv1 = (end > start) ? 1.0f / sm1 : 0.0f;
    float inv2 = (end > start) ? 1.0f / sm2 : 0.0f;
    float inv3 = (end > start) ? 1.0f / sm3 : 0.0f;

    // ---- pass 3: alpha + message accumulation, chunks of 32 edges ----
    int d0 = lane, d1 = lane + 32, d2 = lane + 64;
    int h0 = d0 / DHEAD, h1 = d1 / DHEAD, h2 = d2 / DHEAD;
    float acc0 = 0.f, acc1 = 0.f, acc2 = 0.f;

    for (int base = start; base < end; base += 32) {
        int i = base + lane;
        if (i < end) {
            float4 L = g_elogit[i];
            float a0 = __expf(L.x - mx0) * inv0;
            float a1 = __expf(L.y - mx1) * inv1;
            float a2 = __expf(L.z - mx2) * inv2;
            float a3 = __expf(L.w - mx3) * inv3;
            sh_alpha[wslot][lane][0] = a0;
            sh_alpha[wslot][lane][1] = a1;
            sh_alpha[wslot][lane][2] = a2;
            sh_alpha[wslot][lane][3] = a3;
            sh_p[wslot][lane] = g_csr_packed[i];
            if (alpha_out) {
                reinterpret_cast<float4*>(alpha_out)[g_csr_eid[i]] =
                    make_float4(a0, a1, a2, a3);
            }
        }
        __syncwarp();
        int cnt = min(32, end - base);
        for (int j = 0; j < cnt; j++) {
            unsigned p = sh_p[wslot][j];
            int src = p >> 6;
            int ty = p & 63;
            const float* hs = &g_h[(size_t)src * HID];
            const float* rr = &rel_emb[ty * HID];
            acc0 = fmaf(sh_alpha[wslot][j][h0], hs[d0] + rr[d0], acc0);
            acc1 = fmaf(sh_alpha[wslot][j][h1], hs[d1] + rr[d1], acc1);
            acc2 = fmaf(sh_alpha[wslot][j][h2], hs[d2] + rr[d2], acc2);
        }
        __syncwarp();
    }

    float* orow = out + (size_t)node * HID;
    orow[d0] = gelu_tanh(acc0 + bias[d0]);
    orow[d1] = gelu_tanh(acc1 + bias[d1]);
    orow[d2] = gelu_tanh(acc2 + bias[d2]);
}

extern "C" void kernel_launch(void* const* d_in, const int* in_sizes, int n_in,
                              void* d_out, int out_size) {
    const float* x    = (const float*)d_in[0];
    const int*   ei   = (const int*)d_in[1];   // [2, E]
    const int*   et   = (const int*)d_in[2];   // [E]
    const float* W    = (const float*)d_in[3];
    const float* rel  = (const float*)d_in[4];
    const float* asrc = (const float*)d_in[5];
    const float* adst = (const float*)d_in[6];
    const float* arel = (const float*)d_in[7];
    const float* bias = (const float*)d_in[8];

    int n = in_sizes[0] / HID;
    int e = in_sizes[2];
    int r = in_sizes[4] / HID;
    if (n > NMAX) n = NMAX;
    if (e > EMAX) e = EMAX;

    float* out = (float*)d_out;
    float* alpha_out = (out_size >= n * HID + e * HEADS) ? (out + (size_t)n * HID)
                                                         : nullptr;

    int nscan = (n + SCAN_CHUNK - 1) / SCAN_CHUNK;

    k_gemm<<<(n + 31) / 32, 96>>>(x, W, n);
    k_nodescore<<<(n * HEADS + 255) / 256, 256>>>(asrc, adst, n);
    k_rel<<<(r * HEADS + 255) / 256, 256>>>(rel, arel, r);
    k_zero<<<(n + 255) / 256, 256>>>(n);
    k_count<<<(e + 255) / 256, 256>>>(ei, e);
    k_scan1<<<nscan, SCAN_CHUNK>>>(n);
    k_scan2<<<1, 64>>>(nscan, n);
    k_scan3<<<nscan, SCAN_CHUNK>>>(n);
    k_fill<<<(e + 255) / 256, 256>>>(ei, et, e);
    k_agg<<<(n + 7) / 8, 256>>>(rel, bias, out, alpha_out, n);
}